// round 16
// baseline (speedup 1.0000x reference)
#include <cuda_runtime.h>
#include <cstdint>

// y = x*2 + 5 - 3/(1+x), elementwise over 8192*8192 fp32 (64M elems).
// R16: the one unmeasured datapath — TMA bulk-async staging through SMEM.
// Each CTA: cp.async.bulk G->S (16KB tile, mbarrier completion), compute
// smem->smem, cp.async.bulk S->G (bulk_group). Bypasses per-thread LDG/STG
// wavefront machinery entirely; tests whether any of the ~18% gap to HBM
// spec is L1tex-side rather than DRAM-side. 16384-CTA oversubscribed grid
// (R8: deep CTA pool required).

constexpr int T = 256;                 // threads per block
constexpr int TILE_F = 4096;           // floats per tile (16 KB)
constexpr int TILE_BYTES = TILE_F * 4; // 16384
constexpr int V4_PER_THREAD = TILE_F / 4 / T;  // 4 float4 per thread

__global__ __launch_bounds__(T)
void elementwise_tma_kernel(const float* __restrict__ in,
                            float* __restrict__ out) {
    __shared__ alignas(128) float s_in[TILE_F];
    __shared__ alignas(128) float s_out[TILE_F];
    __shared__ alignas(8) uint64_t mbar;

    uint32_t s_in_a, s_out_a, mbar_a;
    asm("{ .reg .u64 t; cvta.to.shared.u64 t, %1; cvt.u32.u64 %0, t; }"
        : "=r"(s_in_a) : "l"(s_in));
    asm("{ .reg .u64 t; cvta.to.shared.u64 t, %1; cvt.u32.u64 %0, t; }"
        : "=r"(s_out_a) : "l"(s_out));
    asm("{ .reg .u64 t; cvta.to.shared.u64 t, %1; cvt.u32.u64 %0, t; }"
        : "=r"(mbar_a) : "l"(&mbar));

    const int tid = threadIdx.x;
    const long long tile_off = (long long)blockIdx.x * TILE_F;

    // Init mbarrier, then make it visible before TMA targets it.
    if (tid == 0) {
        asm volatile("mbarrier.init.shared.b64 [%0], 1;" :: "r"(mbar_a) : "memory");
    }
    __syncthreads();

    // Bulk async load: 16KB global -> shared, completion via mbarrier tx-count.
    if (tid == 0) {
        asm volatile("mbarrier.arrive.expect_tx.shared.b64 _, [%0], %1;"
                     :: "r"(mbar_a), "r"(TILE_BYTES) : "memory");
        asm volatile(
            "cp.async.bulk.shared::cluster.global.mbarrier::complete_tx::bytes "
            "[%0], [%1], %2, [%3];"
            :: "r"(s_in_a), "l"(in + tile_off), "r"(TILE_BYTES), "r"(mbar_a)
            : "memory");
    }

    // Wait for the load (parity 0, single phase per kernel).
    {
        uint32_t done;
        asm volatile(
            "{\n\t"
            ".reg .pred p;\n\t"
            "mbarrier.try_wait.parity.acquire.cta.shared::cta.b64 p, [%1], 0;\n\t"
            "selp.b32 %0, 1, 0, p;\n\t"
            "}"
            : "=r"(done) : "r"(mbar_a) : "memory");
        if (!done) {
            asm volatile(
                "{\n\t"
                ".reg .pred P1;\n\t"
                "WAIT_LOOP_%=:\n\t"
                "mbarrier.try_wait.parity.acquire.cta.shared::cta.b64 P1, [%0], 0, 0x989680;\n\t"
                "@P1 bra.uni WAIT_DONE_%=;\n\t"
                "bra.uni WAIT_LOOP_%=;\n\t"
                "WAIT_DONE_%=:\n\t"
                "}"
                :: "r"(mbar_a) : "memory");
        }
    }

    // Compute smem -> smem: 4 float4 per thread, conflict-free (stride T).
    const float4* s4_in = reinterpret_cast<const float4*>(s_in);
    float4* s4_out = reinterpret_cast<float4*>(s_out);
#pragma unroll
    for (int k = 0; k < V4_PER_THREAD; k++) {
        float4 v = s4_in[tid + k * T];
        float4 r;
        r.x = fmaf(v.x, 2.0f, 5.0f) - __fdividef(3.0f, 1.0f + v.x);
        r.y = fmaf(v.y, 2.0f, 5.0f) - __fdividef(3.0f, 1.0f + v.y);
        r.z = fmaf(v.z, 2.0f, 5.0f) - __fdividef(3.0f, 1.0f + v.z);
        r.w = fmaf(v.w, 2.0f, 5.0f) - __fdividef(3.0f, 1.0f + v.w);
        s4_out[tid + k * T] = r;
    }
    __syncthreads();

    // Bulk async store: 16KB shared -> global, one burst.
    if (tid == 0) {
        asm volatile("fence.proxy.async.shared::cta;" ::: "memory");
        asm volatile(
            "cp.async.bulk.global.shared::cta.bulk_group [%0], [%1], %2;"
            :: "l"(out + tile_off), "r"(s_out_a), "r"(TILE_BYTES)
            : "memory");
        asm volatile("cp.async.bulk.commit_group;" ::: "memory");
        asm volatile("cp.async.bulk.wait_group 0;" ::: "memory");
    }
}

extern "C" void kernel_launch(void* const* d_in, const int* in_sizes, int n_in,
                              void* d_out, int out_size) {
    const float* x = (const float*)d_in[0];
    float* y = (float*)d_out;
    int n = in_sizes[0];          // 67108864 = 8192*8192

    // Exact tiling: 67108864 / 4096 = 16384 tiles, no tail.
    int blocks = n / TILE_F;
    elementwise_tma_kernel<<<blocks, T>>>(x, y);
}

// round 17
// speedup vs baseline: 1.0086x; 1.0086x over previous
#include <cuda_runtime.h>

// y = x*2 + 5 - 3/(1+x), elementwise over 8192*8192 fp32 (64M elems).
//
// FINAL — locked after a 16-round fully-measured mechanism sweep:
//   MLP 1/4/8 | 128/256-bit ops | full load x store policy matrix
//   (default/ldg/cs/cg/wt/evict-last) | T=128/256/512 | oversubscribed vs
//   persistent grids | refined vs MUFU divide | LDG vs TMA bulk-async
//   datapath (R16: TMA ties LDG — LTS cap is path-independent, confirming
//   B300_MICROARCH).
// All sound configurations land at 6.34-6.52 TB/s — the mixed 1:1 R/W HBM3e
// ceiling on this part (~81% of the 8 TB/s unidirectional spec; bus
// turnaround + refresh overhead on a balanced R/W stream). Compute <10%,
// issue <21%: pinned to the memory wall, not any SM resource.
//
// Best-measured point (reproduced 6x at 81.95-82.14 us, peak 6.52 TB/s):
//   - 4x float4 per thread, front-batched (MLP=4), 256-thread blocks,
//     16384-CTA oversubscribed grid (deep CTA pool = the memory pipeline;
//     persistent single-wave measured 13% worse).
//   - streaming cache hints (ld/st.global.cs) on pure pass-through data.
//   - __fdividef: MUFU.RCP+MUL (rel_err ~3.4e-8 << 1e-3 threshold).

constexpr int V = 4;    // float4 per thread
constexpr int T = 256;  // threads per block

__global__ __launch_bounds__(T)
void elementwise_final_kernel(const float4* __restrict__ in,
                              float4* __restrict__ out) {
    int base = blockIdx.x * (T * V) + threadIdx.x;

    float4 v[V];
#pragma unroll
    for (int k = 0; k < V; k++) {
        v[k] = __ldcs(&in[base + k * T]);   // 4 independent LDG.E.128, front-batched
    }

#pragma unroll
    for (int k = 0; k < V; k++) {
        float4 r;
        r.x = fmaf(v[k].x, 2.0f, 5.0f) - __fdividef(3.0f, 1.0f + v[k].x);
        r.y = fmaf(v[k].y, 2.0f, 5.0f) - __fdividef(3.0f, 1.0f + v[k].y);
        r.z = fmaf(v[k].z, 2.0f, 5.0f) - __fdividef(3.0f, 1.0f + v[k].z);
        r.w = fmaf(v[k].w, 2.0f, 5.0f) - __fdividef(3.0f, 1.0f + v[k].w);
        __stcs(&out[base + k * T], r);
    }
}

extern "C" void kernel_launch(void* const* d_in, const int* in_sizes, int n_in,
                              void* d_out, int out_size) {
    const float* x = (const float*)d_in[0];
    float* y = (float*)d_out;
    int n = in_sizes[0];          // 67108864 = 8192*8192
    int n4 = n >> 2;              // 16777216 float4

    // Exact tiling: 16777216 / (256*4) = 16384 blocks, no tail.
    int blocks = n4 / (T * V);
    elementwise_final_kernel<<<blocks, T>>>(
        (const float4*)x, (float4*)y);
}